// round 15
// baseline (speedup 1.0000x reference)
#include <cuda_runtime.h>
#include <cuda_bf16.h>
#include <cuda_fp16.h>
#include <math.h>
#include <stdint.h>

// Problem constants (fixed by setup_inputs)
#define Bq   2
#define Sq   1024
#define DM   2048
#define NH   16
#define NHKV 4
#define DH   128
#define TOKENS (Bq * Sq)          // 2048
#define NREP (NH / NHKV)          // 4
#define NQKV 3072                 // fused QKV output width
#define KOFF 2048
#define VOFF 2560

// ---------------------------------------------------------------------------
// Scratch (__device__ globals; no allocation allowed)
// ---------------------------------------------------------------------------
__device__ __align__(16) __half g_hid16 [TOKENS * DM];
__device__ __align__(16) __half g_wqkv16[NQKV   * DM];
__device__ __align__(16) __half g_wo16  [DM     * DM];
__device__ float               g_bias   [NQKV];
__device__ __align__(16) __half g_q16[TOKENS * NH   * DH];
__device__ __align__(16) __half g_k16[TOKENS * NHKV * DH];
__device__ __align__(16) __half g_v16[TOKENS * NHKV * DH];
__device__ __align__(16) __half g_ao16[TOKENS * DM];

// ---------------------------------------------------------------------------
// helpers
// ---------------------------------------------------------------------------
__device__ __forceinline__ uint32_t pack_half2f(float x, float y) {
    __half2 h = __floats2half2_rn(x, y);
    return *(uint32_t*)&h;
}

#define LDM_X4(r0,r1,r2,r3,addr) \
    asm volatile("ldmatrix.sync.aligned.m8n8.x4.shared.b16 {%0,%1,%2,%3}, [%4];" \
                 : "=r"(r0),"=r"(r1),"=r"(r2),"=r"(r3) : "r"(addr))
#define LDM_X2(r0,r1,addr) \
    asm volatile("ldmatrix.sync.aligned.m8n8.x2.shared.b16 {%0,%1}, [%2];" \
                 : "=r"(r0),"=r"(r1) : "r"(addr))
#define LDM_X2T(r0,r1,addr) \
    asm volatile("ldmatrix.sync.aligned.m8n8.x2.trans.shared.b16 {%0,%1}, [%2];" \
                 : "=r"(r0),"=r"(r1) : "r"(addr))
#define MMA_F16(c,a0,a1,a2,a3,b0,b1) \
    asm volatile("mma.sync.aligned.m16n8k16.row.col.f32.f16.f16.f32 " \
                 "{%0,%1,%2,%3},{%4,%5,%6,%7},{%8,%9},{%0,%1,%2,%3};" \
                 : "+f"(c[0]),"+f"(c[1]),"+f"(c[2]),"+f"(c[3]) \
                 : "r"(a0),"r"(a1),"r"(a2),"r"(a3),"r"(b0),"r"(b1))

__device__ __forceinline__ void cp_async16(uint32_t dst, const void* src) {
    asm volatile("cp.async.cg.shared.global [%0], [%1], 16;" :: "r"(dst), "l"(src));
}
#define CP_COMMIT() asm volatile("cp.async.commit_group;")
#define CP_WAIT1()  asm volatile("cp.async.wait_group 1;")
#define CP_WAIT0()  asm volatile("cp.async.wait_group 0;")

// ---------------------------------------------------------------------------
// Fused conversion kernel: fp32 -> fp16 for hidden/Wq/Wk/Wv/Wo + bias concat.
// ---------------------------------------------------------------------------
#define CVT_TOTAL 3670784
__global__ __launch_bounds__(256)
void convert_all_kernel(const float* __restrict__ hidden,
                        const float* __restrict__ Wq,
                        const float* __restrict__ Wk,
                        const float* __restrict__ Wv,
                        const float* __restrict__ Wo,
                        const float* __restrict__ bq,
                        const float* __restrict__ bk,
                        const float* __restrict__ bv,
                        __half* __restrict__ hid16,
                        __half* __restrict__ wqkv16,
                        __half* __restrict__ wo16,
                        float* __restrict__ biasq)
{
    long i = (long)blockIdx.x * 256 + threadIdx.x;
    if (i >= CVT_TOTAL) return;

    if (i >= 3670016) {                      // bias concat, fp32
        long j = (i - 3670016) * 4;
        float4 t;
        if (j < 2048)      t = *(const float4*)&bq[j];
        else if (j < 2560) t = *(const float4*)&bk[j - 2048];
        else               t = *(const float4*)&bv[j - 2560];
        *(float4*)&biasq[j] = t;
        return;
    }

    const float* src;
    __half* dst;
    long off;
    if (i < 1048576)      { src = hidden; dst = hid16;                off = i; }
    else if (i < 2097152) { src = Wq;     dst = wqkv16;               off = i - 1048576; }
    else if (i < 2359296) { src = Wk;     dst = wqkv16 + 2048L * DM;  off = i - 2097152; }
    else if (i < 2621440) { src = Wv;     dst = wqkv16 + 2560L * DM;  off = i - 2359296; }
    else                  { src = Wo;     dst = wo16;                 off = i - 2621440; }

    float4 t = ((const float4*)src)[off];
    uint2 h;
    h.x = pack_half2f(t.x, t.y);
    h.y = pack_half2f(t.z, t.w);
    ((uint2*)dst)[off] = h;
}

// ---------------------------------------------------------------------------
// fp16 tensor-core GEMM: 512 threads, 16 warps, warp tile 32x32 (4x4 grid of
// warps over the 128x128 CTA tile), BK=32, cp.async double-buffered.
// 2 CTAs/SM (32 warps) via __launch_bounds__(512, 2).
// Epilogue modes: fuseqkv=0 plain fp32 store; fuseqkv=1 LN/RoPE/layout fusion.
// ---------------------------------------------------------------------------
#define BKP 40
#define TILE16_B (128 * BKP * 2)       // 10240
#define STAGE16_B (2 * TILE16_B)       // 20480 (A + B per stage)
#define SROW 132                       // padded fp32 stage row stride
#define GSMEM 69632                    // max(2*STAGE16_B=40960, 128*SROW*4=67584), padded

__global__ __launch_bounds__(512, 2)
void gemm_f16_kernel(const __half* __restrict__ Ag,
                     const __half* __restrict__ Bg,
                     const float* __restrict__ bias,
                     float* __restrict__ C,
                     int M, int N, int K, int fuseqkv,
                     const float* __restrict__ qn_g,
                     const float* __restrict__ qn_b,
                     const float* __restrict__ kn_g,
                     const float* __restrict__ kn_b,
                     const float* __restrict__ cosp,
                     const float* __restrict__ sinp,
                     __half* __restrict__ q16,
                     __half* __restrict__ k16,
                     __half* __restrict__ v16)
{
    extern __shared__ __half sm16[];
    const uint32_t smBase = (uint32_t)__cvta_generic_to_shared(sm16);

    const int tid  = threadIdx.x;
    const int warp = tid >> 5;
    const int lane = tid & 31;
    const int wm   = (warp >> 2) * 32;        // warp row origin
    const int wn   = (warp & 3) * 32;         // warp col origin
    const int g    = lane >> 2;
    const int tig  = lane & 3;
    const long blkM = (long)blockIdx.y * 128;
    const long blkN = (long)blockIdx.x * 128;

    float acc[2][4][4];
#pragma unroll
    for (int mi = 0; mi < 2; mi++)
#pragma unroll
        for (int ni = 0; ni < 4; ni++)
#pragma unroll
            for (int e = 0; e < 4; e++) acc[mi][ni][e] = 0.f;

    const int aRow = wm + (lane & 15);
    const int aCol = (lane >> 4) * 8;
    const int bRow = wn + (lane & 15);
    const int bCol = (lane >> 4) * 8;

    const int KT = K / 32;

    // loader: 512 chunks (16B) per operand tile, 1 per thread per operand
    const int ldRow = tid >> 2;
    const int ldCol = (tid & 3) * 8;
    const uint32_t ldOff = (uint32_t)(ldRow * BKP + ldCol) * 2;
    const __half* aSrc = Ag + (blkM + ldRow) * (long)K + ldCol;
    const __half* bSrc = Bg + (blkN + ldRow) * (long)K + ldCol;

    {
        cp_async16(smBase + ldOff,            aSrc);
        cp_async16(smBase + TILE16_B + ldOff, bSrc);
        CP_COMMIT();
    }

    for (int kt = 0; kt < KT; kt++) {
        if (kt + 1 < KT) {
            uint32_t st = smBase + ((kt + 1) & 1) * STAGE16_B;
            int k0 = (kt + 1) * 32;
            cp_async16(st + ldOff,            aSrc + k0);
            cp_async16(st + TILE16_B + ldOff, bSrc + k0);
            CP_COMMIT();
            CP_WAIT1();
        } else {
            CP_WAIT0();
        }
        __syncthreads();

        const uint32_t st = smBase + (kt & 1) * STAGE16_B;
#pragma unroll
        for (int kk = 0; kk < 32; kk += 16) {
            uint32_t a[2][4], b[2][4];
#pragma unroll
            for (int mi = 0; mi < 2; mi++) {
                uint32_t off = (uint32_t)(((aRow + mi * 16) * BKP + kk + aCol) * 2);
                LDM_X4(a[mi][0], a[mi][1], a[mi][2], a[mi][3], st + off);
            }
#pragma unroll
            for (int nj = 0; nj < 2; nj++) {
                uint32_t off = (uint32_t)(((bRow + nj * 16) * BKP + kk + bCol) * 2);
                LDM_X4(b[nj][0], b[nj][1], b[nj][2], b[nj][3], st + TILE16_B + off);
            }
#pragma unroll
            for (int mi = 0; mi < 2; mi++)
#pragma unroll
                for (int nj = 0; nj < 2; nj++) {
                    MMA_F16(acc[mi][2 * nj],     a[mi][0], a[mi][1], a[mi][2], a[mi][3],
                            b[nj][0], b[nj][2]);
                    MMA_F16(acc[mi][2 * nj + 1], a[mi][0], a[mi][1], a[mi][2], a[mi][3],
                            b[nj][1], b[nj][3]);
                }
        }
        __syncthreads();
    }

    if (!fuseqkv) {
        // plain epilogue: bias + fp32 store
#pragma unroll
        for (int mi = 0; mi < 2; mi++) {
#pragma unroll
            for (int ni = 0; ni < 4; ni++) {
                long col = blkN + wn + ni * 8 + tig * 2;
                float b0 = bias[col], b1 = bias[col + 1];
                long r0 = blkM + wm + mi * 16 + g;
                long r1 = r0 + 8;
                *(float2*)&C[r0 * N + col] = make_float2(acc[mi][ni][0] + b0, acc[mi][ni][1] + b1);
                *(float2*)&C[r1 * N + col] = make_float2(acc[mi][ni][2] + b0, acc[mi][ni][3] + b1);
            }
        }
        return;
    }

    // ---- fused epilogue: stage tile + bias as fp32 [128][SROW] ----
    float* stage = (float*)sm16;
#pragma unroll
    for (int mi = 0; mi < 2; mi++) {
#pragma unroll
        for (int ni = 0; ni < 4; ni++) {
            int col = wn + ni * 8 + tig * 2;
            float b0 = bias[blkN + col], b1 = bias[blkN + col + 1];
            int r0 = wm + mi * 16 + g;
            int r1 = r0 + 8;
            *(float2*)&stage[r0 * SROW + col] = make_float2(acc[mi][ni][0] + b0, acc[mi][ni][1] + b1);
            *(float2*)&stage[r1 * SROW + col] = make_float2(acc[mi][ni][2] + b0, acc[mi][ni][3] + b1);
        }
    }
    __syncthreads();

    // head identity from N-block
    const int j = (int)blockIdx.x;                 // 0..23
    const int type = (j < 16) ? 0 : ((j < 20) ? 1 : 2);   // q / k / v
    const int h = (type == 0) ? j : ((type == 1) ? j - 16 : j - 20);
    const int nhd = (type == 0) ? NH : NHKV;
    const float prescale = (type == 0) ? 0.08838834764831845f : 1.0f;
    const float* gg = (type == 0) ? qn_g : kn_g;
    const float* bb = (type == 0) ? qn_b : kn_b;
    __half* dst = (type == 0) ? q16 : ((type == 1) ? k16 : v16);

    // warp-per-row LN+RoPE (q/k) or passthrough (v); 8 rows per warp
    for (int rr = 0; rr < 8; rr++) {
        const int r = warp * 8 + rr;
        const long tok = blkM + r;
        const int b = (int)(tok >> 10);
        const int s = (int)(tok & 1023);
        const float* row = stage + r * SROW;
        float e0 = row[lane], e1 = row[lane + 32], e2 = row[lane + 64], e3 = row[lane + 96];
        float r0, r1, r2, r3;
        if (type < 2) {
            float sum = e0 + e1 + e2 + e3;
#pragma unroll
            for (int o = 16; o > 0; o >>= 1) sum += __shfl_xor_sync(0xffffffff, sum, o);
            float mu = sum * (1.0f / DH);
            float d0 = e0 - mu, d1 = e1 - mu, d2 = e2 - mu, d3 = e3 - mu;
            float vs = d0 * d0 + d1 * d1 + d2 * d2 + d3 * d3;
#pragma unroll
            for (int o = 16; o > 0; o >>= 1) vs += __shfl_xor_sync(0xffffffff, vs, o);
            float inv = rsqrtf(vs * (1.0f / DH) + 1e-5f);

            float y0 = d0 * inv * gg[lane]      + bb[lane];
            float y1 = d1 * inv * gg[lane + 32] + bb[lane + 32];
            float y2 = d2 * inv * gg[lane + 64] + bb[lane + 64];
            float y3 = d3 * inv * gg[lane + 96] + bb[lane + 96];

            const float* cs = cosp + (long)s * DH;
            const float* sn = sinp + (long)s * DH;
            float c0 = cs[lane], c1 = cs[lane + 32], c2 = cs[lane + 64], c3 = cs[lane + 96];
            float s0 = sn[lane], s1 = sn[lane + 32], s2 = sn[lane + 64], s3 = sn[lane + 96];

            r0 = (y0 * c0 - y2 * s0) * prescale;
            r1 = (y1 * c1 - y3 * s1) * prescale;
            r2 = (y2 * c2 + y0 * s2) * prescale;
            r3 = (y3 * c3 + y1 * s3) * prescale;
        } else {
            r0 = e0; r1 = e1; r2 = e2; r3 = e3;
        }
        long off = (((long)(b * nhd + h)) * Sq + s) * DH;
        dst[off + lane]      = __float2half_rn(r0);
        dst[off + lane + 32] = __float2half_rn(r1);
        dst[off + lane + 64] = __float2half_rn(r2);
        dst[off + lane + 96] = __float2half_rn(r3);
    }
}

// ---------------------------------------------------------------------------
// Tensor-core causal flash attention, single-pass fp16. (unchanged, verified)
// ---------------------------------------------------------------------------
#define FROWB 272
#define FQ 0
#define FK(buf) (34816 + (buf) * 17408)
#define FV(buf) (69632 + (buf) * 17408)
#define FSMEM 104448

__global__ __launch_bounds__(256)
void flash_tc_kernel(const __half* __restrict__ q16,
                     const __half* __restrict__ k16,
                     const __half* __restrict__ v16,
                     __half* __restrict__ o16)
{
    extern __shared__ char fsm[];
    const uint32_t sb = (uint32_t)__cvta_generic_to_shared(fsm);

    const int tid  = threadIdx.x;
    const int warp = tid >> 5;
    const int lane = tid & 31;
    const int g    = lane >> 2;
    const int tig  = lane & 3;

    const int bh = blockIdx.x & 31;
    const int qt = 7 - (blockIdx.x >> 5);
    const int b  = bh >> 4;
    const int h  = bh & 15;
    const int khd = h >> 2;

    const __half* Qg = q16 + (((long)(b * NH + h)) * Sq + (long)qt * 128) * DH;
    const __half* Kg = k16 + ((long)(b * NHKV + khd)) * Sq * DH;
    const __half* Vg = v16 + ((long)(b * NHKV + khd)) * Sq * DH;

#pragma unroll
    for (int i = 0; i < 8; i++) {
        int idx = tid + i * 256;
        int row = idx >> 4, cg = idx & 15;
        cp_async16(sb + FQ + (uint32_t)(row * FROWB + cg * 16),
                   Qg + row * DH + cg * 8);
    }
    CP_COMMIT();

    {
#pragma unroll
        for (int i = 0; i < 4; i++) {
            int idx = tid + i * 256;
            int row = idx >> 4, cg = idx & 15;
            uint32_t doff = (uint32_t)(row * FROWB + cg * 16);
            long soff = (long)row * DH + cg * 8;
            cp_async16(sb + FK(0) + doff, Kg + soff);
            cp_async16(sb + FV(0) + doff, Vg + soff);
        }
        CP_COMMIT();
    }

    float o[16][4];
#pragma unroll
    for (int nd = 0; nd < 16; nd++)
#pragma unroll
        for (int e = 0; e < 4; e++) o[nd][e] = 0.f;
    float m0 = -1e30f, m1 = -1e30f, l0 = 0.f, l1 = 0.f;

    const int row0 = qt * 128 + warp * 16 + g;
    const int row1 = row0 + 8;

    const uint32_t qA = sb + FQ + (uint32_t)((warp * 16 + (lane & 15)) * FROWB + (lane >> 4) * 16);
    const uint32_t kRowOff = (uint32_t)((lane & 7) * FROWB + ((lane >> 3) & 1) * 16);
    const uint32_t vRowOff = (uint32_t)((lane & 15) * FROWB);

    const int nkt = 2 * qt + 2;
    for (int kt = 0; kt < nkt; kt++) {
        const int buf = kt & 1;
        if (kt + 1 < nkt) {
            const int pb = buf ^ 1;
            const long koff = (long)(kt + 1) * 64 * DH;
#pragma unroll
            for (int i = 0; i < 4; i++) {
                int idx = tid + i * 256;
                int row = idx >> 4, cg = idx & 15;
                uint32_t doff = (uint32_t)(row * FROWB + cg * 16);
                long soff = koff + (long)row * DH + cg * 8;
                cp_async16(sb + FK(pb) + doff, Kg + soff);
                cp_async16(sb + FV(pb) + doff, Vg + soff);
            }
            CP_COMMIT();
            CP_WAIT1();
        } else {
            CP_WAIT0();
        }
        __syncthreads();

        float s[8][4];
#pragma unroll
        for (int j = 0; j < 8; j++)
#pragma unroll
            for (int e = 0; e < 4; e++) s[j][e] = 0.f;

#pragma unroll
        for (int ks = 0; ks < 8; ks++) {
            uint32_t q0, q1, q2, q3;
            LDM_X4(q0, q1, q2, q3, qA + ks * 32);
            const uint32_t kB = sb + FK(buf) + kRowOff + ks * 32;
#pragma unroll
            for (int j = 0; j < 8; j++) {
                uint32_t kb0, kb1;
                LDM_X2(kb0, kb1, kB + j * 8 * FROWB);
                MMA_F16(s[j], q0, q1, q2, q3, kb0, kb1);
            }
        }

        if (kt >= 2 * qt) {
#pragma unroll
            for (int j = 0; j < 8; j++) {
                int c = kt * 64 + j * 8 + 2 * tig;
                if (c     > row0) s[j][0] = -1e30f;
                if (c + 1 > row0) s[j][1] = -1e30f;
                if (c     > row1) s[j][2] = -1e30f;
                if (c + 1 > row1) s[j][3] = -1e30f;
            }
        }

        float rm0 = -1e30f, rm1 = -1e30f;
#pragma unroll
        for (int j = 0; j < 8; j++) {
            rm0 = fmaxf(rm0, fmaxf(s[j][0], s[j][1]));
            rm1 = fmaxf(rm1, fmaxf(s[j][2], s[j][3]));
        }
        rm0 = fmaxf(rm0, __shfl_xor_sync(0xffffffff, rm0, 1));
        rm0 = fmaxf(rm0, __shfl_xor_sync(0xffffffff, rm0, 2));
        rm1 = fmaxf(rm1, __shfl_xor_sync(0xffffffff, rm1, 1));
        rm1 = fmaxf(rm1, __shfl_xor_sync(0xffffffff, rm1, 2));

        float m0n = fmaxf(m0, rm0), m1n = fmaxf(m1, rm1);
        float corr0 = __expf(m0 - m0n), corr1 = __expf(m1 - m1n);
        l0 *= corr0; l1 *= corr1;
#pragma unroll
        for (int nd = 0; nd < 16; nd++) {
            o[nd][0] *= corr0; o[nd][1] *= corr0;
            o[nd][2] *= corr1; o[nd][3] *= corr1;
        }
#pragma unroll
        for (int j = 0; j < 8; j++) {
            s[j][0] = __expf(s[j][0] - m0n);
            s[j][1] = __expf(s[j][1] - m0n);
            s[j][2] = __expf(s[j][2] - m1n);
            s[j][3] = __expf(s[j][3] - m1n);
            l0 += s[j][0] + s[j][1];
            l1 += s[j][2] + s[j][3];
        }
        m0 = m0n; m1 = m1n;

#pragma unroll
        for (int kj = 0; kj < 4; kj++) {
            const int j0 = 2 * kj, j1 = 2 * kj + 1;
            uint32_t a0 = pack_half2f(s[j0][0], s[j0][1]);
            uint32_t a1 = pack_half2f(s[j0][2], s[j0][3]);
            uint32_t a2 = pack_half2f(s[j1][0], s[j1][1]);
            uint32_t a3 = pack_half2f(s[j1][2], s[j1][3]);
            const uint32_t vB = sb + FV(buf) + vRowOff + kj * 16 * FROWB;
#pragma unroll
            for (int nd = 0; nd < 16; nd++) {
                uint32_t vb0, vb1;
                LDM_X2T(vb0, vb1, vB + nd * 16);
                MMA_F16(o[nd], a0, a1, a2, a3, vb0, vb1);
            }
        }
        __syncthreads();
    }

    l0 += __shfl_xor_sync(0xffffffff, l0, 1);
    l0 += __shfl_xor_sync(0xffffffff, l0, 2);
    l1 += __shfl_xor_sync(0xffffffff, l1, 1);
    l1 += __shfl_xor_sync(0xffffffff, l1, 2);
    float inv0 = 1.0f / l0, inv1 = 1.0f / l1;

    const long tok0 = (long)b * Sq + row0;
    long base0 = tok0 * (long)DM + h * DH + 2 * tig;
    long base1 = base0 + 8L * DM;
#pragma unroll
    for (int nd = 0; nd < 16; nd++) {
        *(uint32_t*)&o16[base0 + nd * 8] = pack_half2f(o[nd][0] * inv0, o[nd][1] * inv0);
        *(uint32_t*)&o16[base1 + nd * 8] = pack_half2f(o[nd][2] * inv1, o[nd][3] * inv1);
    }
}

// ---------------------------------------------------------------------------
extern "C" void kernel_launch(void* const* d_in, const int* in_sizes, int n_in,
                              void* d_out, int out_size)
{
    const float* hidden = (const float*)d_in[0];
    const float* cosp   = (const float*)d_in[1];
    const float* sinp   = (const float*)d_in[2];
    const float* Wq     = (const float*)d_in[3];
    const float* bq     = (const float*)d_in[4];
    const float* Wk     = (const float*)d_in[5];
    const float* bk     = (const float*)d_in[6];
    const float* Wv     = (const float*)d_in[7];
    const float* bv     = (const float*)d_in[8];
    const float* Wo     = (const float*)d_in[9];
    const float* bo     = (const float*)d_in[10];
    const float* qn_g   = (const float*)d_in[11];
    const float* qn_b   = (const float*)d_in[12];
    const float* kn_g   = (const float*)d_in[13];
    const float* kn_b   = (const float*)d_in[14];
    float* out = (float*)d_out;

    __half *hid16, *wqkv16, *wo16, *ao16, *q16, *k16, *v16;
    float *biasq;
    cudaGetSymbolAddress((void**)&hid16,  g_hid16);
    cudaGetSymbolAddress((void**)&wqkv16, g_wqkv16);
    cudaGetSymbolAddress((void**)&wo16,   g_wo16);
    cudaGetSymbolAddress((void**)&ao16,   g_ao16);
    cudaGetSymbolAddress((void**)&biasq,  g_bias);
    cudaGetSymbolAddress((void**)&q16,    g_q16);
    cudaGetSymbolAddress((void**)&k16,    g_k16);
    cudaGetSymbolAddress((void**)&v16,    g_v16);

    cudaFuncSetAttribute(gemm_f16_kernel,
                         cudaFuncAttributeMaxDynamicSharedMemorySize, GSMEM);
    cudaFuncSetAttribute(flash_tc_kernel,
                         cudaFuncAttributeMaxDynamicSharedMemorySize, FSMEM);

    // ---- fused fp32 -> fp16 conversions + bias concat (one launch) ----
    convert_all_kernel<<<(CVT_TOTAL + 255) / 256, 256>>>(
        hidden, Wq, Wk, Wv, Wo, bq, bk, bv, hid16, wqkv16, wo16, biasq);

    // ---- fused QKV projection + LN + RoPE + layout (one launch) ----
    {
        dim3 grid(NQKV / 128, TOKENS / 128);
        gemm_f16_kernel<<<grid, 512, GSMEM>>>(hid16, wqkv16, biasq, (float*)0,
                                              TOKENS, NQKV, DM, 1,
                                              qn_g, qn_b, kn_g, kn_b, cosp, sinp,
                                              q16, k16, v16);
    }

    // ---- tensor-core causal flash attention ----
    flash_tc_kernel<<<256, 256, FSMEM>>>(q16, k16, v16, ao16);

    // ---- output projection ----
    {
        dim3 grid(DM / 128, TOKENS / 128);
        gemm_f16_kernel<<<grid, 512, 2 * STAGE16_B>>>(ao16, wo16, bo, out,
                                                      TOKENS, DM, DM, 0,
                                                      qn_g, qn_b, kn_g, kn_b, cosp, sinp,
                                                      q16, k16, v16);
    }
}

// round 16
// speedup vs baseline: 1.0727x; 1.0727x over previous
#include <cuda_runtime.h>
#include <cuda_bf16.h>
#include <cuda_fp16.h>
#include <math.h>
#include <stdint.h>

// Problem constants (fixed by setup_inputs)
#define Bq   2
#define Sq   1024
#define DM   2048
#define NH   16
#define NHKV 4
#define DH   128
#define TOKENS (Bq * Sq)          // 2048
#define NREP (NH / NHKV)          // 4
#define NQKV 3072                 // fused QKV output width
#define KOFF 2048
#define VOFF 2560

// ---------------------------------------------------------------------------
// Scratch (__device__ globals; no allocation allowed)
// ---------------------------------------------------------------------------
__device__ __align__(16) __half g_hid16 [TOKENS * DM];
__device__ __align__(16) __half g_wqkv16[NQKV   * DM];
__device__ __align__(16) __half g_wo16  [DM     * DM];
__device__ float               g_bias   [NQKV];
__device__ __align__(16) __half g_q16[TOKENS * NH   * DH];
__device__ __align__(16) __half g_k16[TOKENS * NHKV * DH];
__device__ __align__(16) __half g_v16[TOKENS * NHKV * DH];
__device__ __align__(16) __half g_ao16[TOKENS * DM];

// ---------------------------------------------------------------------------
// helpers
// ---------------------------------------------------------------------------
__device__ __forceinline__ uint32_t pack_half2f(float x, float y) {
    __half2 h = __floats2half2_rn(x, y);
    return *(uint32_t*)&h;
}

#define LDM_X4(r0,r1,r2,r3,addr) \
    asm volatile("ldmatrix.sync.aligned.m8n8.x4.shared.b16 {%0,%1,%2,%3}, [%4];" \
                 : "=r"(r0),"=r"(r1),"=r"(r2),"=r"(r3) : "r"(addr))
#define LDM_X2(r0,r1,addr) \
    asm volatile("ldmatrix.sync.aligned.m8n8.x2.shared.b16 {%0,%1}, [%2];" \
                 : "=r"(r0),"=r"(r1) : "r"(addr))
#define LDM_X2T(r0,r1,addr) \
    asm volatile("ldmatrix.sync.aligned.m8n8.x2.trans.shared.b16 {%0,%1}, [%2];" \
                 : "=r"(r0),"=r"(r1) : "r"(addr))
#define MMA_F16(c,a0,a1,a2,a3,b0,b1) \
    asm volatile("mma.sync.aligned.m16n8k16.row.col.f32.f16.f16.f32 " \
                 "{%0,%1,%2,%3},{%4,%5,%6,%7},{%8,%9},{%0,%1,%2,%3};" \
                 : "+f"(c[0]),"+f"(c[1]),"+f"(c[2]),"+f"(c[3]) \
                 : "r"(a0),"r"(a1),"r"(a2),"r"(a3),"r"(b0),"r"(b1))

__device__ __forceinline__ void cp_async16(uint32_t dst, const void* src) {
    asm volatile("cp.async.cg.shared.global [%0], [%1], 16;" :: "r"(dst), "l"(src));
}
#define CP_COMMIT() asm volatile("cp.async.commit_group;")
#define CP_WAIT2()  asm volatile("cp.async.wait_group 2;")
#define CP_WAIT1()  asm volatile("cp.async.wait_group 1;")
#define CP_WAIT0()  asm volatile("cp.async.wait_group 0;")

// ---------------------------------------------------------------------------
// Fused conversion kernel: fp32 -> fp16 for hidden/Wq/Wk/Wv/Wo + bias concat.
// ---------------------------------------------------------------------------
#define CVT_TOTAL 3670784
__global__ __launch_bounds__(256)
void convert_all_kernel(const float* __restrict__ hidden,
                        const float* __restrict__ Wq,
                        const float* __restrict__ Wk,
                        const float* __restrict__ Wv,
                        const float* __restrict__ Wo,
                        const float* __restrict__ bq,
                        const float* __restrict__ bk,
                        const float* __restrict__ bv,
                        __half* __restrict__ hid16,
                        __half* __restrict__ wqkv16,
                        __half* __restrict__ wo16,
                        float* __restrict__ biasq)
{
    long i = (long)blockIdx.x * 256 + threadIdx.x;
    if (i >= CVT_TOTAL) return;

    if (i >= 3670016) {                      // bias concat, fp32
        long j = (i - 3670016) * 4;
        float4 t;
        if (j < 2048)      t = *(const float4*)&bq[j];
        else if (j < 2560) t = *(const float4*)&bk[j - 2048];
        else               t = *(const float4*)&bv[j - 2560];
        *(float4*)&biasq[j] = t;
        return;
    }

    const float* src;
    __half* dst;
    long off;
    if (i < 1048576)      { src = hidden; dst = hid16;                off = i; }
    else if (i < 2097152) { src = Wq;     dst = wqkv16;               off = i - 1048576; }
    else if (i < 2359296) { src = Wk;     dst = wqkv16 + 2048L * DM;  off = i - 2097152; }
    else if (i < 2621440) { src = Wv;     dst = wqkv16 + 2560L * DM;  off = i - 2359296; }
    else                  { src = Wo;     dst = wo16;                 off = i - 2621440; }

    float4 t = ((const float4*)src)[off];
    uint2 h;
    h.x = pack_half2f(t.x, t.y);
    h.y = pack_half2f(t.z, t.w);
    ((uint2*)dst)[off] = h;
}

// ---------------------------------------------------------------------------
// fp16 tensor-core GEMM: 256 threads, 8 warps, warp tile 64x32 (R14 tiling),
// BK=32, 4-stage cp.async ring (prefetch distance 3), ONE barrier per K-iter:
//   wait(<=2 own groups) -> __syncthreads -> issue stage kt+3 -> compute kt.
// Epilogue modes: fuseqkv=0 plain fp32 store; fuseqkv=1 LN/RoPE/layout fusion.
// ---------------------------------------------------------------------------
#define BKP 40
#define TILE16_B (128 * BKP * 2)       // 10240
#define STAGE16_B (2 * TILE16_B)       // 20480 (A + B per stage)
#define NSTAGE 4
#define SROW 132                       // padded fp32 stage row stride
#define GSMEM (NSTAGE * STAGE16_B)     // 81920 >= 128*SROW*4 = 67584

__global__ __launch_bounds__(256, 2)
void gemm_f16_kernel(const __half* __restrict__ Ag,
                     const __half* __restrict__ Bg,
                     const float* __restrict__ bias,
                     float* __restrict__ C,
                     int M, int N, int K, int fuseqkv,
                     const float* __restrict__ qn_g,
                     const float* __restrict__ qn_b,
                     const float* __restrict__ kn_g,
                     const float* __restrict__ kn_b,
                     const float* __restrict__ cosp,
                     const float* __restrict__ sinp,
                     __half* __restrict__ q16,
                     __half* __restrict__ k16,
                     __half* __restrict__ v16)
{
    extern __shared__ __half sm16[];
    const uint32_t smBase = (uint32_t)__cvta_generic_to_shared(sm16);

    const int tid  = threadIdx.x;
    const int warp = tid >> 5;
    const int lane = tid & 31;
    const int wm   = (warp >> 2) * 64;
    const int wn   = (warp & 3) * 32;
    const int g    = lane >> 2;
    const int tig  = lane & 3;
    const long blkM = (long)blockIdx.y * 128;
    const long blkN = (long)blockIdx.x * 128;

    float acc[4][4][4];
#pragma unroll
    for (int mi = 0; mi < 4; mi++)
#pragma unroll
        for (int ni = 0; ni < 4; ni++)
#pragma unroll
            for (int e = 0; e < 4; e++) acc[mi][ni][e] = 0.f;

    const int aRow = wm + (lane & 15);
    const int aCol = (lane >> 4) * 8;
    const int bRow = wn + (lane & 7);
    const int bCol = ((lane >> 3) & 1) * 8;

    const int KT = K / 32;

    // loader mapping: 512 16B-chunks per operand tile, 2 per thread
    const int ldRow = (tid << 1) >> 3;          // rows covered via 2 chunks
    // chunk c = tid + i*256: row = c>>2, col = (c&3)*8
    const __half* aBase = Ag + blkM * (long)K;
    const __half* bBase = Bg + blkN * (long)K;

    // prologue: stages 0,1,2
#pragma unroll
    for (int s = 0; s < 3; s++) {
        uint32_t st = smBase + s * STAGE16_B;
        int k0 = s * 32;
#pragma unroll
        for (int i = 0; i < 2; i++) {
            int c = tid + i * 256;
            int row = c >> 2, col = (c & 3) * 8;
            uint32_t d = st + (uint32_t)(row * BKP + col) * 2;
            cp_async16(d,            aBase + (long)row * K + k0 + col);
            cp_async16(d + TILE16_B, bBase + (long)row * K + k0 + col);
        }
        CP_COMMIT();
    }

    for (int kt = 0; kt < KT; kt++) {
        // wait until our own group for stage kt is done (<=2 pending newer)
        int rem = KT - 1 - kt;
        if (rem >= 2)      CP_WAIT2();
        else if (rem == 1) CP_WAIT1();
        else               CP_WAIT0();
        __syncthreads();   // visibility of stage kt + protects stage (kt+3)%4

        if (kt + 3 < KT) {
            uint32_t st = smBase + ((kt + 3) & 3) * STAGE16_B;
            int k0 = (kt + 3) * 32;
#pragma unroll
            for (int i = 0; i < 2; i++) {
                int c = tid + i * 256;
                int row = c >> 2, col = (c & 3) * 8;
                uint32_t d = st + (uint32_t)(row * BKP + col) * 2;
                cp_async16(d,            aBase + (long)row * K + k0 + col);
                cp_async16(d + TILE16_B, bBase + (long)row * K + k0 + col);
            }
            CP_COMMIT();
        }

        const uint32_t st = smBase + (kt & 3) * STAGE16_B;
#pragma unroll
        for (int kk = 0; kk < 32; kk += 16) {
            uint32_t a[4][4], b[4][2];
#pragma unroll
            for (int mi = 0; mi < 4; mi++) {
                uint32_t off = (uint32_t)(((aRow + mi * 16) * BKP + kk + aCol) * 2);
                LDM_X4(a[mi][0], a[mi][1], a[mi][2], a[mi][3], st + off);
            }
#pragma unroll
            for (int ni = 0; ni < 4; ni++) {
                uint32_t off = (uint32_t)(((bRow + ni * 8) * BKP + kk + bCol) * 2);
                LDM_X2(b[ni][0], b[ni][1], st + TILE16_B + off);
            }
#pragma unroll
            for (int mi = 0; mi < 4; mi++)
#pragma unroll
                for (int ni = 0; ni < 4; ni++)
                    MMA_F16(acc[mi][ni], a[mi][0], a[mi][1], a[mi][2], a[mi][3],
                            b[ni][0], b[ni][1]);
        }
    }

    if (!fuseqkv) {
        // plain epilogue: bias + fp32 store (gmem only; no smem hazard)
#pragma unroll
        for (int mi = 0; mi < 4; mi++) {
#pragma unroll
            for (int ni = 0; ni < 4; ni++) {
                long col = blkN + wn + ni * 8 + tig * 2;
                float b0 = bias[col], b1 = bias[col + 1];
                long r0 = blkM + wm + mi * 16 + g;
                long r1 = r0 + 8;
                *(float2*)&C[r0 * N + col] = make_float2(acc[mi][ni][0] + b0, acc[mi][ni][1] + b1);
                *(float2*)&C[r1 * N + col] = make_float2(acc[mi][ni][2] + b0, acc[mi][ni][3] + b1);
            }
        }
        return;
    }

    // ---- fused epilogue: stage tile + bias as fp32 [128][SROW] ----
    __syncthreads();       // all warps done reading smem stages before reuse
    float* stage = (float*)sm16;
#pragma unroll
    for (int mi = 0; mi < 4; mi++) {
#pragma unroll
        for (int ni = 0; ni < 4; ni++) {
            int col = wn + ni * 8 + tig * 2;
            float b0 = bias[blkN + col], b1 = bias[blkN + col + 1];
            int r0 = wm + mi * 16 + g;
            int r1 = r0 + 8;
            *(float2*)&stage[r0 * SROW + col] = make_float2(acc[mi][ni][0] + b0, acc[mi][ni][1] + b1);
            *(float2*)&stage[r1 * SROW + col] = make_float2(acc[mi][ni][2] + b0, acc[mi][ni][3] + b1);
        }
    }
    __syncthreads();

    // head identity from N-block
    const int j = (int)blockIdx.x;                 // 0..23
    const int type = (j < 16) ? 0 : ((j < 20) ? 1 : 2);   // q / k / v
    const int h = (type == 0) ? j : ((type == 1) ? j - 16 : j - 20);
    const int nhd = (type == 0) ? NH : NHKV;
    const float prescale = (type == 0) ? 0.08838834764831845f : 1.0f;
    const float* gg = (type == 0) ? qn_g : kn_g;
    const float* bb = (type == 0) ? qn_b : kn_b;
    __half* dst = (type == 0) ? q16 : ((type == 1) ? k16 : v16);

    // warp-per-row LN+RoPE (q/k) or passthrough (v); 16 rows per warp
    for (int rr = 0; rr < 16; rr++) {
        const int r = warp * 16 + rr;
        const long tok = blkM + r;
        const int b = (int)(tok >> 10);
        const int s = (int)(tok & 1023);
        const float* row = stage + r * SROW;
        float e0 = row[lane], e1 = row[lane + 32], e2 = row[lane + 64], e3 = row[lane + 96];
        float r0, r1, r2, r3;
        if (type < 2) {
            float sum = e0 + e1 + e2 + e3;
#pragma unroll
            for (int o = 16; o > 0; o >>= 1) sum += __shfl_xor_sync(0xffffffff, sum, o);
            float mu = sum * (1.0f / DH);
            float d0 = e0 - mu, d1 = e1 - mu, d2 = e2 - mu, d3 = e3 - mu;
            float vs = d0 * d0 + d1 * d1 + d2 * d2 + d3 * d3;
#pragma unroll
            for (int o = 16; o > 0; o >>= 1) vs += __shfl_xor_sync(0xffffffff, vs, o);
            float inv = rsqrtf(vs * (1.0f / DH) + 1e-5f);

            float y0 = d0 * inv * gg[lane]      + bb[lane];
            float y1 = d1 * inv * gg[lane + 32] + bb[lane + 32];
            float y2 = d2 * inv * gg[lane + 64] + bb[lane + 64];
            float y3 = d3 * inv * gg[lane + 96] + bb[lane + 96];

            const float* cs = cosp + (long)s * DH;
            const float* sn = sinp + (long)s * DH;
            float c0 = cs[lane], c1 = cs[lane + 32], c2 = cs[lane + 64], c3 = cs[lane + 96];
            float s0 = sn[lane], s1 = sn[lane + 32], s2 = sn[lane + 64], s3 = sn[lane + 96];

            r0 = (y0 * c0 - y2 * s0) * prescale;
            r1 = (y1 * c1 - y3 * s1) * prescale;
            r2 = (y2 * c2 + y0 * s2) * prescale;
            r3 = (y3 * c3 + y1 * s3) * prescale;
        } else {
            r0 = e0; r1 = e1; r2 = e2; r3 = e3;
        }
        long off = (((long)(b * nhd + h)) * Sq + s) * DH;
        dst[off + lane]      = __float2half_rn(r0);
        dst[off + lane + 32] = __float2half_rn(r1);
        dst[off + lane + 64] = __float2half_rn(r2);
        dst[off + lane + 96] = __float2half_rn(r3);
    }
}

// ---------------------------------------------------------------------------
// Tensor-core causal flash attention, single-pass fp16. (unchanged, verified)
// ---------------------------------------------------------------------------
#define FROWB 272
#define FQ 0
#define FK(buf) (34816 + (buf) * 17408)
#define FV(buf) (69632 + (buf) * 17408)
#define FSMEM 104448

__global__ __launch_bounds__(256)
void flash_tc_kernel(const __half* __restrict__ q16,
                     const __half* __restrict__ k16,
                     const __half* __restrict__ v16,
                     __half* __restrict__ o16)
{
    extern __shared__ char fsm[];
    const uint32_t sb = (uint32_t)__cvta_generic_to_shared(fsm);

    const int tid  = threadIdx.x;
    const int warp = tid >> 5;
    const int lane = tid & 31;
    const int g    = lane >> 2;
    const int tig  = lane & 3;

    const int bh = blockIdx.x & 31;
    const int qt = 7 - (blockIdx.x >> 5);
    const int b  = bh >> 4;
    const int h  = bh & 15;
    const int khd = h >> 2;

    const __half* Qg = q16 + (((long)(b * NH + h)) * Sq + (long)qt * 128) * DH;
    const __half* Kg = k16 + ((long)(b * NHKV + khd)) * Sq * DH;
    const __half* Vg = v16 + ((long)(b * NHKV + khd)) * Sq * DH;

#pragma unroll
    for (int i = 0; i < 8; i++) {
        int idx = tid + i * 256;
        int row = idx >> 4, cg = idx & 15;
        cp_async16(sb + FQ + (uint32_t)(row * FROWB + cg * 16),
                   Qg + row * DH + cg * 8);
    }
    CP_COMMIT();

    {
#pragma unroll
        for (int i = 0; i < 4; i++) {
            int idx = tid + i * 256;
            int row = idx >> 4, cg = idx & 15;
            uint32_t doff = (uint32_t)(row * FROWB + cg * 16);
            long soff = (long)row * DH + cg * 8;
            cp_async16(sb + FK(0) + doff, Kg + soff);
            cp_async16(sb + FV(0) + doff, Vg + soff);
        }
        CP_COMMIT();
    }

    float o[16][4];
#pragma unroll
    for (int nd = 0; nd < 16; nd++)
#pragma unroll
        for (int e = 0; e < 4; e++) o[nd][e] = 0.f;
    float m0 = -1e30f, m1 = -1e30f, l0 = 0.f, l1 = 0.f;

    const int row0 = qt * 128 + warp * 16 + g;
    const int row1 = row0 + 8;

    const uint32_t qA = sb + FQ + (uint32_t)((warp * 16 + (lane & 15)) * FROWB + (lane >> 4) * 16);
    const uint32_t kRowOff = (uint32_t)((lane & 7) * FROWB + ((lane >> 3) & 1) * 16);
    const uint32_t vRowOff = (uint32_t)((lane & 15) * FROWB);

    const int nkt = 2 * qt + 2;
    for (int kt = 0; kt < nkt; kt++) {
        const int buf = kt & 1;
        if (kt + 1 < nkt) {
            const int pb = buf ^ 1;
            const long koff = (long)(kt + 1) * 64 * DH;
#pragma unroll
            for (int i = 0; i < 4; i++) {
                int idx = tid + i * 256;
                int row = idx >> 4, cg = idx & 15;
                uint32_t doff = (uint32_t)(row * FROWB + cg * 16);
                long soff = koff + (long)row * DH + cg * 8;
                cp_async16(sb + FK(pb) + doff, Kg + soff);
                cp_async16(sb + FV(pb) + doff, Vg + soff);
            }
            CP_COMMIT();
            CP_WAIT1();
        } else {
            CP_WAIT0();
        }
        __syncthreads();

        float s[8][4];
#pragma unroll
        for (int j = 0; j < 8; j++)
#pragma unroll
            for (int e = 0; e < 4; e++) s[j][e] = 0.f;

#pragma unroll
        for (int ks = 0; ks < 8; ks++) {
            uint32_t q0, q1, q2, q3;
            LDM_X4(q0, q1, q2, q3, qA + ks * 32);
            const uint32_t kB = sb + FK(buf) + kRowOff + ks * 32;
#pragma unroll
            for (int j = 0; j < 8; j++) {
                uint32_t kb0, kb1;
                LDM_X2(kb0, kb1, kB + j * 8 * FROWB);
                MMA_F16(s[j], q0, q1, q2, q3, kb0, kb1);
            }
        }

        if (kt >= 2 * qt) {
#pragma unroll
            for (int j = 0; j < 8; j++) {
                int c = kt * 64 + j * 8 + 2 * tig;
                if (c     > row0) s[j][0] = -1e30f;
                if (c + 1 > row0) s[j][1] = -1e30f;
                if (c     > row1) s[j][2] = -1e30f;
                if (c + 1 > row1) s[j][3] = -1e30f;
            }
        }

        float rm0 = -1e30f, rm1 = -1e30f;
#pragma unroll
        for (int j = 0; j < 8; j++) {
            rm0 = fmaxf(rm0, fmaxf(s[j][0], s[j][1]));
            rm1 = fmaxf(rm1, fmaxf(s[j][2], s[j][3]));
        }
        rm0 = fmaxf(rm0, __shfl_xor_sync(0xffffffff, rm0, 1));
        rm0 = fmaxf(rm0, __shfl_xor_sync(0xffffffff, rm0, 2));
        rm1 = fmaxf(rm1, __shfl_xor_sync(0xffffffff, rm1, 1));
        rm1 = fmaxf(rm1, __shfl_xor_sync(0xffffffff, rm1, 2));

        float m0n = fmaxf(m0, rm0), m1n = fmaxf(m1, rm1);
        float corr0 = __expf(m0 - m0n), corr1 = __expf(m1 - m1n);
        l0 *= corr0; l1 *= corr1;
#pragma unroll
        for (int nd = 0; nd < 16; nd++) {
            o[nd][0] *= corr0; o[nd][1] *= corr0;
            o[nd][2] *= corr1; o[nd][3] *= corr1;
        }
#pragma unroll
        for (int j = 0; j < 8; j++) {
            s[j][0] = __expf(s[j][0] - m0n);
            s[j][1] = __expf(s[j][1] - m0n);
            s[j][2] = __expf(s[j][2] - m1n);
            s[j][3] = __expf(s[j][3] - m1n);
            l0 += s[j][0] + s[j][1];
            l1 += s[j][2] + s[j][3];
        }
        m0 = m0n; m1 = m1n;

#pragma unroll
        for (int kj = 0; kj < 4; kj++) {
            const int j0 = 2 * kj, j1 = 2 * kj + 1;
            uint32_t a0 = pack_half2f(s[j0][0], s[j0][1]);
            uint32_t a1 = pack_half2f(s[j0][2], s[j0][3]);
            uint32_t a2 = pack_half2f(s[j1][0], s[j1][1]);
            uint32_t a3 = pack_half2f(s[j1][2], s[j1][3]);
            const uint32_t vB = sb + FV(buf) + vRowOff + kj * 16 * FROWB;
#pragma unroll
            for (int nd = 0; nd < 16; nd++) {
                uint32_t vb0, vb1;
                LDM_X2T(vb0, vb1, vB + nd * 16);
                MMA_F16(o[nd], a0, a1, a2, a3, vb0, vb1);
            }
        }
        __syncthreads();
    }

    l0 += __shfl_xor_sync(0xffffffff, l0, 1);
    l0 += __shfl_xor_sync(0xffffffff, l0, 2);
    l1 += __shfl_xor_sync(0xffffffff, l1, 1);
    l1 += __shfl_xor_sync(0xffffffff, l1, 2);
    float inv0 = 1.0f / l0, inv1 = 1.0f / l1;

    const long tok0 = (long)b * Sq + row0;
    long base0 = tok0 * (long)DM + h * DH + 2 * tig;
    long base1 = base0 + 8L * DM;
#pragma unroll
    for (int nd = 0; nd < 16; nd++) {
        *(uint32_t*)&o16[base0 + nd * 8] = pack_half2f(o[nd][0] * inv0, o[nd][1] * inv0);
        *(uint32_t*)&o16[base1 + nd * 8] = pack_half2f(o[nd][2] * inv1, o[nd][3] * inv1);
    }
}

// ---------------------------------------------------------------------------
extern "C" void kernel_launch(void* const* d_in, const int* in_sizes, int n_in,
                              void* d_out, int out_size)
{
    const float* hidden = (const float*)d_in[0];
    const float* cosp   = (const float*)d_in[1];
    const float* sinp   = (const float*)d_in[2];
    const float* Wq     = (const float*)d_in[3];
    const float* bq     = (const float*)d_in[4];
    const float* Wk     = (const float*)d_in[5];
    const float* bk     = (const float*)d_in[6];
    const float* Wv     = (const float*)d_in[7];
    const float* bv     = (const float*)d_in[8];
    const float* Wo     = (const float*)d_in[9];
    const float* bo     = (const float*)d_in[10];
    const float* qn_g   = (const float*)d_in[11];
    const float* qn_b   = (const float*)d_in[12];
    const float* kn_g   = (const float*)d_in[13];
    const float* kn_b   = (const float*)d_in[14];
    float* out = (float*)d_out;

    __half *hid16, *wqkv16, *wo16, *ao16, *q16, *k16, *v16;
    float *biasq;
    cudaGetSymbolAddress((void**)&hid16,  g_hid16);
    cudaGetSymbolAddress((void**)&wqkv16, g_wqkv16);
    cudaGetSymbolAddress((void**)&wo16,   g_wo16);
    cudaGetSymbolAddress((void**)&ao16,   g_ao16);
    cudaGetSymbolAddress((void**)&biasq,  g_bias);
    cudaGetSymbolAddress((void**)&q16,    g_q16);
    cudaGetSymbolAddress((void**)&k16,    g_k16);
    cudaGetSymbolAddress((void**)&v16,    g_v16);

    cudaFuncSetAttribute(gemm_f16_kernel,
                         cudaFuncAttributeMaxDynamicSharedMemorySize, GSMEM);
    cudaFuncSetAttribute(flash_tc_kernel,
                         cudaFuncAttributeMaxDynamicSharedMemorySize, FSMEM);

    // ---- fused fp32 -> fp16 conversions + bias concat (one launch) ----
    convert_all_kernel<<<(CVT_TOTAL + 255) / 256, 256>>>(
        hidden, Wq, Wk, Wv, Wo, bq, bk, bv, hid16, wqkv16, wo16, biasq);

    // ---- fused QKV projection + LN + RoPE + layout (one launch) ----
    {
        dim3 grid(NQKV / 128, TOKENS / 128);
        gemm_f16_kernel<<<grid, 256, GSMEM>>>(hid16, wqkv16, biasq, (float*)0,
                                              TOKENS, NQKV, DM, 1,
                                              qn_g, qn_b, kn_g, kn_b, cosp, sinp,
                                              q16, k16, v16);
    }

    // ---- tensor-core causal flash attention ----
    flash_tc_kernel<<<256, 256, FSMEM>>>(q16, k16, v16, ao16);

    // ---- output projection ----
    {
        dim3 grid(DM / 128, TOKENS / 128);
        gemm_f16_kernel<<<grid, 256, GSMEM>>>(ao16, wo16, bo, out,
                                              TOKENS, DM, DM, 0,
                                              qn_g, qn_b, kn_g, kn_b, cosp, sinp,
                                              q16, k16, v16);
    }
}

// round 17
// speedup vs baseline: 1.0957x; 1.0215x over previous
#include <cuda_runtime.h>
#include <cuda_bf16.h>
#include <cuda_fp16.h>
#include <math.h>
#include <stdint.h>

// Problem constants (fixed by setup_inputs)
#define Bq   2
#define Sq   1024
#define DM   2048
#define NH   16
#define NHKV 4
#define DH   128
#define TOKENS (Bq * Sq)          // 2048
#define NREP (NH / NHKV)          // 4
#define NQKV 3072                 // fused QKV output width
#define KOFF 2048
#define VOFF 2560

// ---------------------------------------------------------------------------
// Scratch (__device__ globals; no allocation allowed)
// ---------------------------------------------------------------------------
__device__ __align__(16) __half g_hid16 [TOKENS * DM];
__device__ __align__(16) __half g_wqkv16[NQKV   * DM];
__device__ __align__(16) __half g_wo16  [DM     * DM];
__device__ float               g_bias   [NQKV];
__device__ __align__(16) __half g_q16[TOKENS * NH   * DH];
__device__ __align__(16) __half g_k16[TOKENS * NHKV * DH];
__device__ __align__(16) __half g_v16[TOKENS * NHKV * DH];
__device__ __align__(16) __half g_ao16[TOKENS * DM];

// ---------------------------------------------------------------------------
// helpers
// ---------------------------------------------------------------------------
__device__ __forceinline__ uint32_t pack_half2f(float x, float y) {
    __half2 h = __floats2half2_rn(x, y);
    return *(uint32_t*)&h;
}

#define LDM_X4(r0,r1,r2,r3,addr) \
    asm volatile("ldmatrix.sync.aligned.m8n8.x4.shared.b16 {%0,%1,%2,%3}, [%4];" \
                 : "=r"(r0),"=r"(r1),"=r"(r2),"=r"(r3) : "r"(addr))
#define LDM_X2(r0,r1,addr) \
    asm volatile("ldmatrix.sync.aligned.m8n8.x2.shared.b16 {%0,%1}, [%2];" \
                 : "=r"(r0),"=r"(r1) : "r"(addr))
#define LDM_X2T(r0,r1,addr) \
    asm volatile("ldmatrix.sync.aligned.m8n8.x2.trans.shared.b16 {%0,%1}, [%2];" \
                 : "=r"(r0),"=r"(r1) : "r"(addr))
#define MMA_F16(c,a0,a1,a2,a3,b0,b1) \
    asm volatile("mma.sync.aligned.m16n8k16.row.col.f32.f16.f16.f32 " \
                 "{%0,%1,%2,%3},{%4,%5,%6,%7},{%8,%9},{%0,%1,%2,%3};" \
                 : "+f"(c[0]),"+f"(c[1]),"+f"(c[2]),"+f"(c[3]) \
                 : "r"(a0),"r"(a1),"r"(a2),"r"(a3),"r"(b0),"r"(b1))

__device__ __forceinline__ void cp_async16(uint32_t dst, const void* src) {
    asm volatile("cp.async.cg.shared.global [%0], [%1], 16;" :: "r"(dst), "l"(src));
}
#define CP_COMMIT() asm volatile("cp.async.commit_group;")
#define CP_WAIT1()  asm volatile("cp.async.wait_group 1;")
#define CP_WAIT0()  asm volatile("cp.async.wait_group 0;")

// ---------------------------------------------------------------------------
// Fused conversion kernel: fp32 -> fp16 for hidden/Wq/Wk/Wv/Wo + bias concat.
// ---------------------------------------------------------------------------
#define CVT_TOTAL 3670784
__global__ __launch_bounds__(256)
void convert_all_kernel(const float* __restrict__ hidden,
                        const float* __restrict__ Wq,
                        const float* __restrict__ Wk,
                        const float* __restrict__ Wv,
                        const float* __restrict__ Wo,
                        const float* __restrict__ bq,
                        const float* __restrict__ bk,
                        const float* __restrict__ bv,
                        __half* __restrict__ hid16,
                        __half* __restrict__ wqkv16,
                        __half* __restrict__ wo16,
                        float* __restrict__ biasq)
{
    long i = (long)blockIdx.x * 256 + threadIdx.x;
    if (i >= CVT_TOTAL) return;

    if (i >= 3670016) {                      // bias concat, fp32
        long j = (i - 3670016) * 4;
        float4 t;
        if (j < 2048)      t = *(const float4*)&bq[j];
        else if (j < 2560) t = *(const float4*)&bk[j - 2048];
        else               t = *(const float4*)&bv[j - 2560];
        *(float4*)&biasq[j] = t;
        return;
    }

    const float* src;
    __half* dst;
    long off;
    if (i < 1048576)      { src = hidden; dst = hid16;                off = i; }
    else if (i < 2097152) { src = Wq;     dst = wqkv16;               off = i - 1048576; }
    else if (i < 2359296) { src = Wk;     dst = wqkv16 + 2048L * DM;  off = i - 2097152; }
    else if (i < 2621440) { src = Wv;     dst = wqkv16 + 2560L * DM;  off = i - 2359296; }
    else                  { src = Wo;     dst = wo16;                 off = i - 2621440; }

    float4 t = ((const float4*)src)[off];
    uint2 h;
    h.x = pack_half2f(t.x, t.y);
    h.y = pack_half2f(t.z, t.w);
    ((uint2*)dst)[off] = h;
}

// ---------------------------------------------------------------------------
// fp16 tensor-core GEMM: 256 threads, 8 warps, warp tile 64x32, BK=64,
// 2-stage cp.async double buffer. B operands via paired ldmatrix.x4
// (6 ldmatrix per 4 k16-steps instead of 8). Accumulation order (k16
// ascending) identical to previous rounds -> bit-identical results.
// Epilogue modes: fuseqkv=0 plain fp32 store; fuseqkv=1 LN/RoPE/layout fusion.
// ---------------------------------------------------------------------------
#define BKP 72                          // halfs per smem row (144B, 16B-aligned)
#define TILE16_B (128 * BKP * 2)        // 18432 bytes per operand tile
#define STAGE16_B (2 * TILE16_B)        // 36864 (A + B per stage)
#define SROW 132                        // padded fp32 stage row stride
#define GSMEM (2 * STAGE16_B)           // 73728 >= 128*SROW*4 = 67584

__global__ __launch_bounds__(256, 2)
void gemm_f16_kernel(const __half* __restrict__ Ag,
                     const __half* __restrict__ Bg,
                     const float* __restrict__ bias,
                     float* __restrict__ C,
                     int M, int N, int K, int fuseqkv,
                     const float* __restrict__ qn_g,
                     const float* __restrict__ qn_b,
                     const float* __restrict__ kn_g,
                     const float* __restrict__ kn_b,
                     const float* __restrict__ cosp,
                     const float* __restrict__ sinp,
                     __half* __restrict__ q16,
                     __half* __restrict__ k16,
                     __half* __restrict__ v16)
{
    extern __shared__ __half sm16[];
    const uint32_t smBase = (uint32_t)__cvta_generic_to_shared(sm16);

    const int tid  = threadIdx.x;
    const int warp = tid >> 5;
    const int lane = tid & 31;
    const int wm   = (warp >> 2) * 64;
    const int wn   = (warp & 3) * 32;
    const int g    = lane >> 2;
    const int tig  = lane & 3;
    const long blkM = (long)blockIdx.y * 128;
    const long blkN = (long)blockIdx.x * 128;

    float acc[4][4][4];
#pragma unroll
    for (int mi = 0; mi < 4; mi++)
#pragma unroll
        for (int ni = 0; ni < 4; ni++)
#pragma unroll
            for (int e = 0; e < 4; e++) acc[mi][ni][e] = 0.f;

    // ldmatrix addressing
    const int aRow = wm + (lane & 15);
    const int aCol = (lane >> 4) * 8;          // 0 or 8 (halfs)
    const int bRow = wn + (lane & 15);         // x4-paired B rows
    const int bCol = (lane >> 4) * 8;

    const int KT = K >> 6;                     // BK=64

    // loader: 1024 16B-chunks per operand tile, 4 per thread per operand
    const __half* aBase = Ag + blkM * (long)K;
    const __half* bBase = Bg + blkN * (long)K;

    {
        uint32_t st = smBase;
#pragma unroll
        for (int i = 0; i < 4; i++) {
            int c = tid + i * 256;
            int row = c >> 3, c8 = c & 7;
            uint32_t d = st + (uint32_t)(row * (BKP * 2) + c8 * 16);
            cp_async16(d,            aBase + (long)row * K + c8 * 8);
            cp_async16(d + TILE16_B, bBase + (long)row * K + c8 * 8);
        }
        CP_COMMIT();
    }

    for (int kt = 0; kt < KT; kt++) {
        if (kt + 1 < KT) {
            uint32_t st = smBase + ((kt + 1) & 1) * STAGE16_B;
            int k0 = (kt + 1) << 6;
#pragma unroll
            for (int i = 0; i < 4; i++) {
                int c = tid + i * 256;
                int row = c >> 3, c8 = c & 7;
                uint32_t d = st + (uint32_t)(row * (BKP * 2) + c8 * 16);
                cp_async16(d,            aBase + (long)row * K + k0 + c8 * 8);
                cp_async16(d + TILE16_B, bBase + (long)row * K + k0 + c8 * 8);
            }
            CP_COMMIT();
            CP_WAIT1();
        } else {
            CP_WAIT0();
        }
        __syncthreads();

        const uint32_t st = smBase + (kt & 1) * STAGE16_B;
#pragma unroll
        for (int kk = 0; kk < 64; kk += 16) {
            uint32_t a[4][4], b[2][4];
#pragma unroll
            for (int mi = 0; mi < 4; mi++) {
                uint32_t off = (uint32_t)((aRow + mi * 16) * (BKP * 2) + (kk + aCol) * 2);
                LDM_X4(a[mi][0], a[mi][1], a[mi][2], a[mi][3], st + off);
            }
#pragma unroll
            for (int nj = 0; nj < 2; nj++) {
                uint32_t off = (uint32_t)((bRow + nj * 16) * (BKP * 2) + (kk + bCol) * 2);
                LDM_X4(b[nj][0], b[nj][1], b[nj][2], b[nj][3], st + TILE16_B + off);
            }
#pragma unroll
            for (int mi = 0; mi < 4; mi++)
#pragma unroll
                for (int nj = 0; nj < 2; nj++) {
                    MMA_F16(acc[mi][2 * nj],     a[mi][0], a[mi][1], a[mi][2], a[mi][3],
                            b[nj][0], b[nj][2]);
                    MMA_F16(acc[mi][2 * nj + 1], a[mi][0], a[mi][1], a[mi][2], a[mi][3],
                            b[nj][1], b[nj][3]);
                }
        }
        __syncthreads();
    }

    if (!fuseqkv) {
        // plain epilogue: bias + fp32 store
#pragma unroll
        for (int mi = 0; mi < 4; mi++) {
#pragma unroll
            for (int ni = 0; ni < 4; ni++) {
                long col = blkN + wn + ni * 8 + tig * 2;
                float b0 = bias[col], b1 = bias[col + 1];
                long r0 = blkM + wm + mi * 16 + g;
                long r1 = r0 + 8;
                *(float2*)&C[r0 * N + col] = make_float2(acc[mi][ni][0] + b0, acc[mi][ni][1] + b1);
                *(float2*)&C[r1 * N + col] = make_float2(acc[mi][ni][2] + b0, acc[mi][ni][3] + b1);
            }
        }
        return;
    }

    // ---- fused epilogue: stage tile + bias as fp32 [128][SROW] ----
    float* stage = (float*)sm16;
#pragma unroll
    for (int mi = 0; mi < 4; mi++) {
#pragma unroll
        for (int ni = 0; ni < 4; ni++) {
            int col = wn + ni * 8 + tig * 2;
            float b0 = bias[blkN + col], b1 = bias[blkN + col + 1];
            int r0 = wm + mi * 16 + g;
            int r1 = r0 + 8;
            *(float2*)&stage[r0 * SROW + col] = make_float2(acc[mi][ni][0] + b0, acc[mi][ni][1] + b1);
            *(float2*)&stage[r1 * SROW + col] = make_float2(acc[mi][ni][2] + b0, acc[mi][ni][3] + b1);
        }
    }
    __syncthreads();

    // head identity from N-block
    const int j = (int)blockIdx.x;                 // 0..23
    const int type = (j < 16) ? 0 : ((j < 20) ? 1 : 2);   // q / k / v
    const int h = (type == 0) ? j : ((type == 1) ? j - 16 : j - 20);
    const int nhd = (type == 0) ? NH : NHKV;
    const float prescale = (type == 0) ? 0.08838834764831845f : 1.0f;
    const float* gg = (type == 0) ? qn_g : kn_g;
    const float* bb = (type == 0) ? qn_b : kn_b;
    __half* dst = (type == 0) ? q16 : ((type == 1) ? k16 : v16);

    // warp-per-row LN+RoPE (q/k) or passthrough (v); 16 rows per warp
    for (int rr = 0; rr < 16; rr++) {
        const int r = warp * 16 + rr;
        const long tok = blkM + r;
        const int b = (int)(tok >> 10);
        const int s = (int)(tok & 1023);
        const float* row = stage + r * SROW;
        float e0 = row[lane], e1 = row[lane + 32], e2 = row[lane + 64], e3 = row[lane + 96];
        float r0, r1, r2, r3;
        if (type < 2) {
            float sum = e0 + e1 + e2 + e3;
#pragma unroll
            for (int o = 16; o > 0; o >>= 1) sum += __shfl_xor_sync(0xffffffff, sum, o);
            float mu = sum * (1.0f / DH);
            float d0 = e0 - mu, d1 = e1 - mu, d2 = e2 - mu, d3 = e3 - mu;
            float vs = d0 * d0 + d1 * d1 + d2 * d2 + d3 * d3;
#pragma unroll
            for (int o = 16; o > 0; o >>= 1) vs += __shfl_xor_sync(0xffffffff, vs, o);
            float inv = rsqrtf(vs * (1.0f / DH) + 1e-5f);

            float y0 = d0 * inv * gg[lane]      + bb[lane];
            float y1 = d1 * inv * gg[lane + 32] + bb[lane + 32];
            float y2 = d2 * inv * gg[lane + 64] + bb[lane + 64];
            float y3 = d3 * inv * gg[lane + 96] + bb[lane + 96];

            const float* cs = cosp + (long)s * DH;
            const float* sn = sinp + (long)s * DH;
            float c0 = cs[lane], c1 = cs[lane + 32], c2 = cs[lane + 64], c3 = cs[lane + 96];
            float s0 = sn[lane], s1 = sn[lane + 32], s2 = sn[lane + 64], s3 = sn[lane + 96];

            r0 = (y0 * c0 - y2 * s0) * prescale;
            r1 = (y1 * c1 - y3 * s1) * prescale;
            r2 = (y2 * c2 + y0 * s2) * prescale;
            r3 = (y3 * c3 + y1 * s3) * prescale;
        } else {
            r0 = e0; r1 = e1; r2 = e2; r3 = e3;
        }
        long off = (((long)(b * nhd + h)) * Sq + s) * DH;
        dst[off + lane]      = __float2half_rn(r0);
        dst[off + lane + 32] = __float2half_rn(r1);
        dst[off + lane + 64] = __float2half_rn(r2);
        dst[off + lane + 96] = __float2half_rn(r3);
    }
}

// ---------------------------------------------------------------------------
// Tensor-core causal flash attention, single-pass fp16. (unchanged, verified)
// ---------------------------------------------------------------------------
#define FROWB 272
#define FQ 0
#define FK(buf) (34816 + (buf) * 17408)
#define FV(buf) (69632 + (buf) * 17408)
#define FSMEM 104448

__global__ __launch_bounds__(256)
void flash_tc_kernel(const __half* __restrict__ q16,
                     const __half* __restrict__ k16,
                     const __half* __restrict__ v16,
                     __half* __restrict__ o16)
{
    extern __shared__ char fsm[];
    const uint32_t sb = (uint32_t)__cvta_generic_to_shared(fsm);

    const int tid  = threadIdx.x;
    const int warp = tid >> 5;
    const int lane = tid & 31;
    const int g    = lane >> 2;
    const int tig  = lane & 3;

    const int bh = blockIdx.x & 31;
    const int qt = 7 - (blockIdx.x >> 5);
    const int b  = bh >> 4;
    const int h  = bh & 15;
    const int khd = h >> 2;

    const __half* Qg = q16 + (((long)(b * NH + h)) * Sq + (long)qt * 128) * DH;
    const __half* Kg = k16 + ((long)(b * NHKV + khd)) * Sq * DH;
    const __half* Vg = v16 + ((long)(b * NHKV + khd)) * Sq * DH;

#pragma unroll
    for (int i = 0; i < 8; i++) {
        int idx = tid + i * 256;
        int row = idx >> 4, cg = idx & 15;
        cp_async16(sb + FQ + (uint32_t)(row * FROWB + cg * 16),
                   Qg + row * DH + cg * 8);
    }
    CP_COMMIT();

    {
#pragma unroll
        for (int i = 0; i < 4; i++) {
            int idx = tid + i * 256;
            int row = idx >> 4, cg = idx & 15;
            uint32_t doff = (uint32_t)(row * FROWB + cg * 16);
            long soff = (long)row * DH + cg * 8;
            cp_async16(sb + FK(0) + doff, Kg + soff);
            cp_async16(sb + FV(0) + doff, Vg + soff);
        }
        CP_COMMIT();
    }

    float o[16][4];
#pragma unroll
    for (int nd = 0; nd < 16; nd++)
#pragma unroll
        for (int e = 0; e < 4; e++) o[nd][e] = 0.f;
    float m0 = -1e30f, m1 = -1e30f, l0 = 0.f, l1 = 0.f;

    const int row0 = qt * 128 + warp * 16 + g;
    const int row1 = row0 + 8;

    const uint32_t qA = sb + FQ + (uint32_t)((warp * 16 + (lane & 15)) * FROWB + (lane >> 4) * 16);
    const uint32_t kRowOff = (uint32_t)((lane & 7) * FROWB + ((lane >> 3) & 1) * 16);
    const uint32_t vRowOff = (uint32_t)((lane & 15) * FROWB);

    const int nkt = 2 * qt + 2;
    for (int kt = 0; kt < nkt; kt++) {
        const int buf = kt & 1;
        if (kt + 1 < nkt) {
            const int pb = buf ^ 1;
            const long koff = (long)(kt + 1) * 64 * DH;
#pragma unroll
            for (int i = 0; i < 4; i++) {
                int idx = tid + i * 256;
                int row = idx >> 4, cg = idx & 15;
                uint32_t doff = (uint32_t)(row * FROWB + cg * 16);
                long soff = koff + (long)row * DH + cg * 8;
                cp_async16(sb + FK(pb) + doff, Kg + soff);
                cp_async16(sb + FV(pb) + doff, Vg + soff);
            }
            CP_COMMIT();
            CP_WAIT1();
        } else {
            CP_WAIT0();
        }
        __syncthreads();

        float s[8][4];
#pragma unroll
        for (int j = 0; j < 8; j++)
#pragma unroll
            for (int e = 0; e < 4; e++) s[j][e] = 0.f;

#pragma unroll
        for (int ks = 0; ks < 8; ks++) {
            uint32_t q0, q1, q2, q3;
            LDM_X4(q0, q1, q2, q3, qA + ks * 32);
            const uint32_t kB = sb + FK(buf) + kRowOff + ks * 32;
#pragma unroll
            for (int j = 0; j < 8; j++) {
                uint32_t kb0, kb1;
                LDM_X2(kb0, kb1, kB + j * 8 * FROWB);
                MMA_F16(s[j], q0, q1, q2, q3, kb0, kb1);
            }
        }

        if (kt >= 2 * qt) {
#pragma unroll
            for (int j = 0; j < 8; j++) {
                int c = kt * 64 + j * 8 + 2 * tig;
                if (c     > row0) s[j][0] = -1e30f;
                if (c + 1 > row0) s[j][1] = -1e30f;
                if (c     > row1) s[j][2] = -1e30f;
                if (c + 1 > row1) s[j][3] = -1e30f;
            }
        }

        float rm0 = -1e30f, rm1 = -1e30f;
#pragma unroll
        for (int j = 0; j < 8; j++) {
            rm0 = fmaxf(rm0, fmaxf(s[j][0], s[j][1]));
            rm1 = fmaxf(rm1, fmaxf(s[j][2], s[j][3]));
        }
        rm0 = fmaxf(rm0, __shfl_xor_sync(0xffffffff, rm0, 1));
        rm0 = fmaxf(rm0, __shfl_xor_sync(0xffffffff, rm0, 2));
        rm1 = fmaxf(rm1, __shfl_xor_sync(0xffffffff, rm1, 1));
        rm1 = fmaxf(rm1, __shfl_xor_sync(0xffffffff, rm1, 2));

        float m0n = fmaxf(m0, rm0), m1n = fmaxf(m1, rm1);
        float corr0 = __expf(m0 - m0n), corr1 = __expf(m1 - m1n);
        l0 *= corr0; l1 *= corr1;
#pragma unroll
        for (int nd = 0; nd < 16; nd++) {
            o[nd][0] *= corr0; o[nd][1] *= corr0;
            o[nd][2] *= corr1; o[nd][3] *= corr1;
        }
#pragma unroll
        for (int j = 0; j < 8; j++) {
            s[j][0] = __expf(s[j][0] - m0n);
            s[j][1] = __expf(s[j][1] - m0n);
            s[j][2] = __expf(s[j][2] - m1n);
            s[j][3] = __expf(s[j][3] - m1n);
            l0 += s[j][0] + s[j][1];
            l1 += s[j][2] + s[j][3];
        }
        m0 = m0n; m1 = m1n;

#pragma unroll
        for (int kj = 0; kj < 4; kj++) {
            const int j0 = 2 * kj, j1 = 2 * kj + 1;
            uint32_t a0 = pack_half2f(s[j0][0], s[j0][1]);
            uint32_t a1 = pack_half2f(s[j0][2], s[j0][3]);
            uint32_t a2 = pack_half2f(s[j1][0], s[j1][1]);
            uint32_t a3 = pack_half2f(s[j1][2], s[j1][3]);
            const uint32_t vB = sb + FV(buf) + vRowOff + kj * 16 * FROWB;
#pragma unroll
            for (int nd = 0; nd < 16; nd++) {
                uint32_t vb0, vb1;
                LDM_X2T(vb0, vb1, vB + nd * 16);
                MMA_F16(o[nd], a0, a1, a2, a3, vb0, vb1);
            }
        }
        __syncthreads();
    }

    l0 += __shfl_xor_sync(0xffffffff, l0, 1);
    l0 += __shfl_xor_sync(0xffffffff, l0, 2);
    l1 += __shfl_xor_sync(0xffffffff, l1, 1);
    l1 += __shfl_xor_sync(0xffffffff, l1, 2);
    float inv0 = 1.0f / l0, inv1 = 1.0f / l1;

    const long tok0 = (long)b * Sq + row0;
    long base0 = tok0 * (long)DM + h * DH + 2 * tig;
    long base1 = base0 + 8L * DM;
#pragma unroll
    for (int nd = 0; nd < 16; nd++) {
        *(uint32_t*)&o16[base0 + nd * 8] = pack_half2f(o[nd][0] * inv0, o[nd][1] * inv0);
        *(uint32_t*)&o16[base1 + nd * 8] = pack_half2f(o[nd][2] * inv1, o[nd][3] * inv1);
    }
}

// ---------------------------------------------------------------------------
extern "C" void kernel_launch(void* const* d_in, const int* in_sizes, int n_in,
                              void* d_out, int out_size)
{
    const float* hidden = (const float*)d_in[0];
    const float* cosp   = (const float*)d_in[1];
    const float* sinp   = (const float*)d_in[2];
    const float* Wq     = (const float*)d_in[3];
    const float* bq     = (const float*)d_in[4];
    const float* Wk     = (const float*)d_in[5];
    const float* bk     = (const float*)d_in[6];
    const float* Wv     = (const float*)d_in[7];
    const float* bv     = (const float*)d_in[8];
    const float* Wo     = (const float*)d_in[9];
    const float* bo     = (const float*)d_in[10];
    const float* qn_g   = (const float*)d_in[11];
    const float* qn_b   = (const float*)d_in[12];
    const float* kn_g   = (const float*)d_in[13];
    const float* kn_b   = (const float*)d_in[14];
    float* out = (float*)d_out;

    __half *hid16, *wqkv16, *wo16, *ao16, *q16, *k16, *v16;
    float *biasq;
    cudaGetSymbolAddress((void**)&hid16,  g_hid16);
    cudaGetSymbolAddress((void**)&wqkv16, g_wqkv16);
    cudaGetSymbolAddress((void**)&wo16,   g_wo16);
    cudaGetSymbolAddress((void**)&ao16,   g_ao16);
    cudaGetSymbolAddress((void**)&biasq,  g_bias);
    cudaGetSymbolAddress((void**)&q16,    g_q16);
    cudaGetSymbolAddress((void**)&k16,    g_k16);
    cudaGetSymbolAddress((void**)&v16,    g_v16);

    cudaFuncSetAttribute(gemm_f16_kernel,
                         cudaFuncAttributeMaxDynamicSharedMemorySize, GSMEM);
    cudaFuncSetAttribute(flash_tc_kernel,
                         cudaFuncAttributeMaxDynamicSharedMemorySize, FSMEM);

    // ---- fused fp32 -> fp16 conversions + bias concat (one launch) ----
    convert_all_kernel<<<(CVT_TOTAL + 255) / 256, 256>>>(
        hidden, Wq, Wk, Wv, Wo, bq, bk, bv, hid16, wqkv16, wo16, biasq);

    // ---- fused QKV projection + LN + RoPE + layout (one launch) ----
    {
        dim3 grid(NQKV / 128, TOKENS / 128);
        gemm_f16_kernel<<<grid, 256, GSMEM>>>(hid16, wqkv16, biasq, (float*)0,
                                              TOKENS, NQKV, DM, 1,
                                              qn_g, qn_b, kn_g, kn_b, cosp, sinp,
                                              q16, k16, v16);
    }

    // ---- tensor-core causal flash attention ----
    flash_tc_kernel<<<256, 256, FSMEM>>>(q16, k16, v16, ao16);

    // ---- output projection ----
    {
        dim3 grid(DM / 128, TOKENS / 128);
        gemm_f16_kernel<<<grid, 256, GSMEM>>>(ao16, wo16, bo, out,
                                              TOKENS, DM, DM, 0,
                                              qn_g, qn_b, kn_g, kn_b, cosp, sinp,
                                              q16, k16, v16);
    }
}